// round 6
// baseline (speedup 1.0000x reference)
#include <cuda_runtime.h>

// Rician NLL fused elementwise + full reduction, single kernel.
//   out = -sum( log(I0(e*o*inv_var)) - 0.5*inv_var*e^2 )
// 268 MB streamed -> HBM-bound. Last-block-done pattern removes the
// 4.8us standalone final-reduce launch seen in R5 ncu.

#define NB 1184   // 8 blocks per SM on 148 SMs
#define NT 256

__device__ float        d_partials[NB];
__device__ unsigned int d_count = 0;   // reset to 0 by last block each call

// log(I0(x)) via Abramowitz & Stegun 9.8.1/9.8.2 (fp32, rel err ~2e-7).
// Inputs are uniform[0,1) products -> always the small branch; large branch
// kept for robustness only.
__device__ __forceinline__ float log_i0f(float x) {
    float ax = fabsf(x);
    if (ax < 3.75f) {
        float t = ax * (1.0f / 3.75f);
        t *= t;
        float p = 1.0f + t * (3.5156229f + t * (3.0899424f + t * (1.2067492f
                + t * (0.2659732f + t * (0.0360768f + t * 0.0045813f)))));
        return __logf(p);
    } else {
        float ti = 3.75f / ax;
        float p = 0.39894228f + ti * (0.01328592f + ti * (0.00225319f
                + ti * (-0.00157565f + ti * (0.00916281f + ti * (-0.02057706f
                + ti * (0.02635537f + ti * (-0.01647633f + ti * 0.00392377f)))))));
        return ax - 0.5f * __logf(ax) + __logf(p);
    }
}

__device__ __forceinline__ float block_reduce(float acc, float* sdata) {
    #pragma unroll
    for (int off = 16; off > 0; off >>= 1)
        acc += __shfl_down_sync(0xffffffffu, acc, off);
    const int lane = threadIdx.x & 31;
    const int wid  = threadIdx.x >> 5;
    if (lane == 0) sdata[wid] = acc;
    __syncthreads();
    if (wid == 0) {
        acc = (lane < NT / 32) ? sdata[lane] : 0.0f;
        #pragma unroll
        for (int off = 16; off > 0; off >>= 1)
            acc += __shfl_down_sync(0xffffffffu, acc, off);
    }
    return acc;  // valid in thread 0
}

__global__ __launch_bounds__(NT)
void nll_kernel(const float* __restrict__ est,
                const float* __restrict__ obs,
                const float* __restrict__ std_noise,
                float* __restrict__ out,
                int n) {
    const float s = std_noise[0];
    const float inv_var  = 1.0f / (s * s);
    const float half_inv = 0.5f * inv_var;

    float acc = 0.0f;
    const int n4 = n >> 2;
    const float4* __restrict__ e4 = (const float4*)est;
    const float4* __restrict__ o4 = (const float4*)obs;

    const int stride = gridDim.x * blockDim.x;
    for (int i = blockIdx.x * blockDim.x + threadIdx.x; i < n4; i += stride) {
        float4 e = __ldcs(&e4[i]);   // streaming: working set >> L2, no reuse
        float4 o = __ldcs(&o4[i]);
        acc += log_i0f(e.x * o.x * inv_var) - half_inv * e.x * e.x;
        acc += log_i0f(e.y * o.y * inv_var) - half_inv * e.y * e.y;
        acc += log_i0f(e.z * o.z * inv_var) - half_inv * e.z * e.z;
        acc += log_i0f(e.w * o.w * inv_var) - half_inv * e.w * e.w;
    }
    // scalar tail (empty for n = 2^25, kept for generality)
    for (int i = (n4 << 2) + blockIdx.x * blockDim.x + threadIdx.x; i < n; i += stride) {
        float e = est[i], o = obs[i];
        acc += log_i0f(e * o * inv_var) - half_inv * e * e;
    }

    __shared__ float sdata[NT / 32];
    acc = block_reduce(acc, sdata);

    // ── last-block-done final reduce (deterministic: fixed summation order;
    //    the atomic only selects WHICH block finishes) ──
    __shared__ bool is_last;
    if (threadIdx.x == 0) {
        d_partials[blockIdx.x] = acc;
        __threadfence();                       // publish partial before count
        unsigned int v = atomicAdd(&d_count, 1u);
        is_last = (v == (unsigned int)(gridDim.x - 1));
    }
    __syncthreads();

    if (is_last) {
        float a = 0.0f;
        for (int i = threadIdx.x; i < NB; i += NT)
            a += __ldcg(&d_partials[i]);       // L2 read, bypass L1
        __syncthreads();                       // sdata reuse barrier
        a = block_reduce(a, sdata);
        if (threadIdx.x == 0) {
            out[0]  = -a;
            d_count = 0;                       // re-arm for next graph replay
        }
    }
}

extern "C" void kernel_launch(void* const* d_in, const int* in_sizes, int n_in,
                              void* d_out, int out_size) {
    const float* est = (const float*)d_in[0];
    const float* obs = (const float*)d_in[1];
    const float* sn  = (const float*)d_in[2];
    const int n = in_sizes[0];

    nll_kernel<<<NB, NT>>>(est, obs, sn, (float*)d_out, n);
}